// round 9
// baseline (speedup 1.0000x reference)
#include <cuda_runtime.h>
#include <cuda_fp16.h>
#include <stdint.h>

#define BATCH 16
#define CIN   128
#define HH    128
#define WW    128
#define OCH   256
#define HW    (HH*WW)
#define KTOT  1152.0f
#define BADCNT 576.0f

// ---------------- scratch (no allocations allowed) ----------------
__device__ float g_pm  [BATCH*HW];
__device__ float g_bad [BATCH*HW];
__device__ float g_csum[BATCH*HW];
__device__ float g_ccnt[BATCH*HW];
// B fragments (single fp16 chain) for mma.sync m16n8k16:
// [ tap*4+cg ][ nt32 ][ kt2 ][ lane32 ][ reg2 ]  (u32 = 2 fp16); block = 4096 words
#define WF_WORDS (36*4096)
__device__ uint32_t g_wf[WF_WORDS];

__device__ __forceinline__ bool nan_bits(float v) {
    return (__float_as_uint(v) & 0x7fffffffu) > 0x7f800000u;
}
__device__ __forceinline__ uint32_t smem_u32(const void* p) {
    return (uint32_t)__cvta_generic_to_shared(p);
}
__device__ __forceinline__ void cp16(uint32_t dst, const void* src) {
    asm volatile("cp.async.cg.shared.global [%0], [%1], 16;" :: "r"(dst), "l"(src));
}
__device__ __forceinline__ void mma16816(float* c, const uint32_t* a, const uint32_t* b) {
    asm volatile(
        "mma.sync.aligned.m16n8k16.row.col.f32.f16.f16.f32 "
        "{%0,%1,%2,%3}, {%4,%5,%6,%7}, {%8,%9}, {%0,%1,%2,%3};"
        : "+f"(c[0]), "+f"(c[1]), "+f"(c[2]), "+f"(c[3])
        : "r"(a[0]), "r"(a[1]), "r"(a[2]), "r"(a[3]), "r"(b[0]), "r"(b[1]));
}

// ---------------- stats kernels ----------------
__global__ void stats1_kernel(const float* __restrict__ x) {
    int idx = blockIdx.x * blockDim.x + threadIdx.x;
    if (idx >= BATCH * HW) return;
    int b  = idx / HW;
    int hw = idx - b * HW;
    const float* xp = x + (size_t)b * CIN * HW + hw;
    float s = 0.f, cnt = 0.f;
    #pragma unroll 8
    for (int c = 0; c < CIN; c++) {
        float v = xp[(size_t)c * HW];
        bool n = nan_bits(v);
        cnt += n ? 1.f : 0.f;
        s   += n ? 0.f : v;
    }
    g_csum[idx] = s;
    g_ccnt[idx] = cnt;
}

__global__ void stats2_kernel() {
    int idx = blockIdx.x * blockDim.x + threadIdx.x;
    if (idx >= BATCH * HW) return;
    int b  = idx / HW;
    int hw = idx - b * HW;
    int oh = hw / WW;
    int ow = hw - oh * WW;
    float vs = 0.f, cnt = 0.f;
    #pragma unroll
    for (int kh = -1; kh <= 1; kh++) {
        int ih = oh + kh;
        if (ih < 0 || ih >= HH) continue;
        #pragma unroll
        for (int kw = -1; kw <= 1; kw++) {
            int iw = ow + kw;
            if (iw < 0 || iw >= WW) continue;
            int g = b * HW + ih * WW + iw;
            vs  += g_csum[g];
            cnt += g_ccnt[g];
        }
    }
    float valid = KTOT - cnt;
    g_pm[idx]  = vs / fmaxf(valid, 1.f);
    g_bad[idx] = (cnt >= BADCNT) ? 1.f : 0.f;
}

// ---------------- weight prep: fp16 round into B-fragment layout ----------------
__global__ void wprep_kernel(const float* __restrict__ w) {
    int idx = blockIdx.x * blockDim.x + threadIdx.x;
    if (idx >= WF_WORDS) return;
    int r    = idx & 1;                // k-half: r0 k=0..7, r1 k=8..15
    int lane = (idx >> 1) & 31;
    int kt   = (idx >> 6) & 1;
    int nt   = (idx >> 7) & 31;
    int tcg  = idx >> 12;              // tap*4+cg
    int cg   = tcg & 3;
    int tap  = tcg >> 2;

    int oc = nt * 8 + (lane >> 2);
    int c0 = cg * 32 + kt * 16 + (lane & 3) * 2 + r * 8;

    uint32_t pack = 0;
    #pragma unroll
    for (int e = 0; e < 2; e++) {
        float wv = w[((size_t)oc * CIN + (c0 + e)) * 9 + tap];
        pack |= (uint32_t)__half_as_ushort(__float2half_rn(wv)) << (e * 16);
    }
    g_wf[idx] = pack;
}

// ---------------- main conv: row-pipelined fp16 mma.sync implicit GEMM ----------------
// CTA: 512 thr, 16 warps (2m x 8n). M=128 pixels (one row) x N=256 ocs. K=1152.
// Row granularity: 12 "rows" (cg 0..3 x kh 0..2); each row = 3 kw taps.
#define THREADS 512
#define RAWPAD 34
#define RAWBYTES (132*RAWPAD*2)   // 8976

#define OFF_BF   0u               // 2 x (3 x 16384) = 98304
#define OFF_AF   98304u           // 2 x (3 x 8192)  = 49152
#define OFF_RAW  147456u          // 3 x 8976 = 26928
#define OFF_PMH  174384u          // 256
#define OFF_BAD  174640u          // 512
#define OFF_BIAS 175152u          // 1024
#define SMEMSZ   176176u

__device__ __forceinline__ void stage_load(float* v, const float* __restrict__ x,
                                           int b, int oh, int R, int tid) {
    int cg = R >> 2; cg = R / 3; int kh = R - cg * 3;
    int rin = oh + kh - 1;
    bool rowok = (rin >= 0) & (rin < HH);
    const float* xrow = x + ((size_t)(b * CIN + cg * 32) * HH + rin) * WW;
    #pragma unroll
    for (int it = 0; it < 9; it++) {
        int i = tid + it * THREADS;
        float val = 0.f;
        if (i < 32 * 132) {
            int c = i / 132;
            int col = i - c * 132 - 1;
            if (rowok && col >= 0 && col < WW) val = xrow[(size_t)c * HW + col];
        }
        v[it] = val;
    }
}

__device__ __forceinline__ void stage_store(const float* v, uint16_t* raw, int tid) {
    #pragma unroll
    for (int it = 0; it < 9; it++) {
        int i = tid + it * THREADS;
        if (i < 32 * 132) {
            int c  = i / 132;
            int wc = i - c * 132;
            raw[wc * RAWPAD + c] = __half_as_ushort(__float2half_rn(v[it]));
        }
    }
}

__device__ __forceinline__ void build_af(uint32_t* af, const uint16_t* raw,
                                         const uint16_t* pmh, int kw, int tid) {
    // a0:{m,k} a1:{m+8,k} a2:{m,k+8} a3:{m+8,k+8}
    #pragma unroll
    for (int it = 0; it < 4; it++) {
        int w    = tid + it * THREADS;
        int reg  = w & 3;
        int ln   = (w >> 2) & 31;
        int tile = w >> 7;            // mt*2 + kt
        int kt   = tile & 1;
        int mt   = tile >> 1;
        int m    = mt * 16 + ((reg & 1) << 3) + (ln >> 2);
        int k    = kt * 16 + ((reg >> 1) << 3) + (ln & 3) * 2;
        uint32_t pair = *(const uint32_t*)&raw[(m + kw) * RAWPAD + k];
        uint32_t pmv  = (uint32_t)pmh[m];
        uint32_t lo = pair & 0xffffu, hi = pair >> 16;
        if ((lo & 0x7fffu) > 0x7c00u) lo = pmv;
        if ((hi & 0x7fffu) > 0x7c00u) hi = pmv;
        af[w] = (hi << 16) | lo;
    }
}

__device__ __forceinline__ void build3(uint32_t* af, const uint16_t* raw,
                                       const uint16_t* pmh, int tid) {
    build_af(af,        raw, pmh, 0, tid);
    build_af(af + 2048, raw, pmh, 1, tid);
    build_af(af + 4096, raw, pmh, 2, tid);
}

__device__ __forceinline__ void issue_bf3(uint32_t bf_addr, int R, int tid) {
    int cg = R / 3, kh = R - cg * 3;
    #pragma unroll
    for (int kw = 0; kw < 3; kw++) {
        int tcg = (kh * 3 + kw) * 4 + cg;
        const char* src = (const char*)g_wf + (size_t)tcg * 16384;
        uint32_t d = bf_addr + (uint32_t)kw * 16384u + (uint32_t)tid * 16u;
        cp16(d,        src + tid * 16);
        cp16(d + 8192, src + 8192 + tid * 16);
    }
    asm volatile("cp.async.commit_group;");
}

__device__ __forceinline__ void mma_tap(float acc[4][4][4], const uint32_t* af,
                                        const uint32_t* bf, int mt0, int nt0, int lane) {
    #pragma unroll
    for (int kt = 0; kt < 2; kt++) {
        uint32_t a[4][4];
        #pragma unroll
        for (int i = 0; i < 4; i++) {
            uint4 av = *(const uint4*)&af[(((mt0 + i) * 2 + kt) * 32 + lane) * 4];
            a[i][0] = av.x; a[i][1] = av.y; a[i][2] = av.z; a[i][3] = av.w;
        }
        #pragma unroll
        for (int j = 0; j < 4; j++) {
            uint2 bv = *(const uint2*)&bf[(((nt0 + j) * 2 + kt) * 32 + lane) * 2];
            uint32_t bb[2] = {bv.x, bv.y};
            #pragma unroll
            for (int i = 0; i < 4; i++)
                mma16816(acc[i][j], a[i], bb);
        }
    }
}

__device__ __forceinline__ void mma3(float acc[4][4][4], const uint32_t* af,
                                     const uint32_t* bf, int mt0, int nt0, int lane) {
    mma_tap(acc, af,        bf,        mt0, nt0, lane);
    mma_tap(acc, af + 2048, bf + 4096, mt0, nt0, lane);
    mma_tap(acc, af + 4096, bf + 8192, mt0, nt0, lane);
}

__global__ __launch_bounds__(THREADS, 1)
void conv_mma_kernel(const float* __restrict__ x,
                     const float* __restrict__ bias,
                     float* __restrict__ out)
{
    extern __shared__ char sm[];
    uint32_t* s_bfb[2] = {(uint32_t*)(sm + OFF_BF), (uint32_t*)(sm + OFF_BF + 49152)};
    uint32_t* s_afb[2] = {(uint32_t*)(sm + OFF_AF), (uint32_t*)(sm + OFF_AF + 24576)};
    uint16_t* s_raw3[3] = {(uint16_t*)(sm + OFF_RAW),
                           (uint16_t*)(sm + OFF_RAW + RAWBYTES),
                           (uint16_t*)(sm + OFF_RAW + 2 * RAWBYTES)};
    uint16_t* s_pmh  = (uint16_t*)(sm + OFF_PMH);
    float*    s_bad  = (float*)(sm + OFF_BAD);
    float*    s_bias = (float*)(sm + OFF_BIAS);
    const uint32_t smb = smem_u32(sm);

    const int tid  = threadIdx.x;
    const int lane = tid & 31;
    const int wid  = tid >> 5;
    const int oh   = blockIdx.x;
    const int b    = blockIdx.y;
    const int mt0  = (wid >> 3) * 4;   // 0 or 4
    const int nt0  = (wid & 7) * 4;    // 0,4,...,28

    if (tid < 128) {
        int g = b * HW + oh * WW + tid;
        s_pmh[tid] = __half_as_ushort(__float2half_rn(g_pm[g]));
        s_bad[tid] = g_bad[g];
    }
    if (tid < 256) s_bias[tid] = bias[tid];

    float acc[4][4][4];
    #pragma unroll
    for (int i = 0; i < 4; i++)
        #pragma unroll
        for (int j = 0; j < 4; j++)
            #pragma unroll
            for (int r = 0; r < 4; r++) acc[i][j][r] = 0.f;

    float v[9];
    // prologue: stage rows 0,1; build row 0 (buffer 0)
    stage_load(v, x, b, oh, 0, tid); stage_store(v, s_raw3[0], tid);
    stage_load(v, x, b, oh, 1, tid); stage_store(v, s_raw3[1], tid);
    __syncthreads();
    issue_bf3(smb + OFF_BF, 0, tid);
    build3(s_afb[0], s_raw3[0], s_pmh, tid);
    asm volatile("cp.async.wait_group 0;");
    __syncthreads();

    int p = 0;
    for (int R = 0; R < 12; R++) {
        if (R < 11) issue_bf3(smb + OFF_BF + (uint32_t)(p ^ 1) * 49152u, R + 1, tid);
        if (R < 10) stage_load(v, x, b, oh, R + 2, tid);   // LDG early
        if (R < 11) build3(s_afb[p ^ 1], s_raw3[(R + 1) % 3], s_pmh, tid);
        mma3(acc, s_afb[p], s_bfb[p], mt0, nt0, lane);
        if (R < 10) stage_store(v, s_raw3[(R + 2) % 3], tid); // STS after MMA
        asm volatile("cp.async.wait_group 0;");
        __syncthreads();
        p ^= 1;
    }

    // ---- epilogue: bias + bad->NaN, direct stores ----
    const float NANF = __uint_as_float(0x7fc00000u);
    #pragma unroll
    for (int i = 0; i < 4; i++) {
        #pragma unroll
        for (int r = 0; r < 4; r++) {
            int m = (mt0 + i) * 16 + ((r >> 1) << 3) + (lane >> 2);
            bool isbad = s_bad[m] != 0.f;
            #pragma unroll
            for (int j = 0; j < 4; j++) {
                int n = (nt0 + j) * 8 + (lane & 3) * 2 + (r & 1);
                float vv = acc[i][j][r] + s_bias[n];
                out[(((size_t)b * OCH + n) * HH + oh) * WW + m] = isbad ? NANF : vv;
            }
        }
    }
}

// ---------------------------------------------------------------------------
extern "C" void kernel_launch(void* const* d_in, const int* in_sizes, int n_in,
                              void* d_out, int out_size) {
    const float* x    = (const float*)d_in[0];
    const float* wk   = (const float*)d_in[1];
    const float* bias = (const float*)d_in[2];
    float* out        = (float*)d_out;

    int npix = BATCH * HW;
    stats1_kernel<<<(npix + 255) / 256, 256>>>(x);
    stats2_kernel<<<(npix + 255) / 256, 256>>>();
    wprep_kernel<<<(WF_WORDS + 255) / 256, 256>>>(wk);

    cudaFuncSetAttribute(conv_mma_kernel,
                         cudaFuncAttributeMaxDynamicSharedMemorySize, SMEMSZ);
    dim3 grid(HH, BATCH);
    conv_mma_kernel<<<grid, THREADS, SMEMSZ>>>(x, bias, out);
}